// round 4
// baseline (speedup 1.0000x reference)
#include <cuda_runtime.h>
#include <math.h>

#define NTOK 8192
#define DDIM 768
#define NEXP 16
#define D4   192              // DDIM/4
#define TPB  16               // tokens per block
#define NBLK (NTOK / TPB)     // 512 blocks
#define EPS  1e-5f

// ---------------- device scratch (no allocations allowed) ----------------
__device__ float g_partials[NBLK * 32];        // per-block soft[16] + hard[16]
__device__ float g_scratch[NTOK * NEXP + 64];  // fallback sink if out layout differs

__device__ __forceinline__ float quad_get(const float4 v, const int c) {
    return (c == 0) ? v.x : (c == 1) ? v.y : (c == 2) ? v.z : v.w;
}

// ---------------- fused gate + combine ----------------
// 512 blocks x 256 threads, 16 tokens per block. Static smem = exactly 48KB:
// sW holds W for phase 1; after the last sW read, its first 96 floats are
// reused as sGate (16 x float4) + sAcc (32 floats).
__global__ __launch_bounds__(256) void moe_fused_kernel(
    const float* __restrict__ f,
    const float* __restrict__ x,
    const float* __restrict__ W,
    const float* __restrict__ b,
    float* __restrict__ y,
    float* __restrict__ s_out)
{
    __shared__ float4 sW[3072];          // 48KB: W as float4 [e*192 + i]
    float4* sGate = sW;                  // floats [0..64)  -- aliased AFTER sW reads
    float*  sAcc  = (float*)sW + 64;     // floats [64..96) -- aliased AFTER sW reads

    const int tid = threadIdx.x;
    const int n0  = blockIdx.x * TPB;

    // ---- stage W: 3072 float4, 12 per thread, coalesced ----
    const float4* W4 = (const float4*)W;
    #pragma unroll
    for (int i = tid; i < 3072; i += 256) sW[i] = W4[i];
    __syncthreads();

    const int t = tid >> 4;              // local token 0..15
    const int s = tid & 15;              // D-slice 0..15 (48 floats each)
    const int n = n0 + t;

    float acc[NEXP];
    #pragma unroll
    for (int e = 0; e < NEXP; e++) acc[e] = 0.f;

    const float4* x4   = (const float4*)x;
    const size_t xbase = (size_t)n * D4 + s * 12;
    const int    wbase = s * 12;

    #pragma unroll
    for (int i = 0; i < 12; i++) {
        const float4 xv = x4[xbase + i];
        #pragma unroll
        for (int e = 0; e < NEXP; e++) {
            const float4 wv = sW[e * D4 + wbase + i];
            acc[e] += xv.x * wv.x + xv.y * wv.y + xv.z * wv.z + xv.w * wv.w;
        }
    }

    // reduce across the 16 slice-lanes (lanes 16t..16t+15 share a token)
    #pragma unroll
    for (int e = 0; e < NEXP; e++) {
        acc[e] += __shfl_xor_sync(0xffffffffu, acc[e], 1);
        acc[e] += __shfl_xor_sync(0xffffffffu, acc[e], 2);
        acc[e] += __shfl_xor_sync(0xffffffffu, acc[e], 4);
        acc[e] += __shfl_xor_sync(0xffffffffu, acc[e], 8);
    }

    __syncthreads();                     // ALL sW reads retired; safe to alias

    float w0 = 0.f, w1 = 0.f;
    int   e0 = 0,   e1 = 0;
    const bool leader = (s == 0);

    if (tid < 32) sAcc[tid] = 0.f;       // disjoint from sGate region

    if (leader) {
        float v[NEXP];
        #pragma unroll
        for (int e = 0; e < NEXP; e++) v[e] = acc[e] + b[e];

        // top-2 (ties -> lowest index first, matching lax.top_k)
        float b0 = v[0], b1 = -INFINITY;
        e0 = 0; e1 = -1;
        #pragma unroll
        for (int e = 1; e < NEXP; e++) {
            if (v[e] > b0)      { b1 = b0; e1 = e0; b0 = v[e]; e0 = e; }
            else if (v[e] > b1) { b1 = v[e]; e1 = e; }
        }
        // stable softmax over the 2 selected logits (b1 <= b0)
        const float tt  = expf(b1 - b0);
        const float inv = 1.f / (1.f + tt);
        w0 = inv;
        w1 = tt * inv;

        float4 gt;
        gt.x = w0; gt.y = w1;
        gt.z = __int_as_float(e0);
        gt.w = __int_as_float(e1);
        sGate[t] = gt;

        // s_concat row: 1 where g < eps else 0 (g = 0 for unselected experts)
        float4* srow = (float4*)(s_out + (size_t)n * NEXP);
        #pragma unroll
        for (int qq = 0; qq < 4; qq++) {
            float4 sv;
            #pragma unroll
            for (int c = 0; c < 4; c++) {
                const int e = qq * 4 + c;
                const float ge  = (e == e0) ? w0 : ((e == e1) ? w1 : 0.f);
                const float val = (ge < EPS) ? 1.f : 0.f;
                if      (c == 0) sv.x = val;
                else if (c == 1) sv.y = val;
                else if (c == 2) sv.z = val;
                else             sv.w = val;
            }
            srow[qq] = sv;
        }
    }

    __syncthreads();                     // sAcc zeroed + sGate written
    if (leader) {
        atomicAdd(&sAcc[e0], w0);
        atomicAdd(&sAcc[e1], w1);
        atomicAdd(&sAcc[16 + e0], (w0 < EPS) ? 0.f : 1.f);
        atomicAdd(&sAcc[16 + e1], (w1 < EPS) ? 0.f : 1.f);
    }
    __syncthreads();
    if (tid < 32) g_partials[blockIdx.x * 32 + tid] = sAcc[tid];

    // ---- phase 2: sparse combine for this block's 16 tokens ----
    const float4* f4 = (const float4*)f;
    #pragma unroll 1
    for (int tk = 0; tk < TPB; tk++) {
        const float4 gt  = sGate[tk];
        const float gw0 = gt.x, gw1 = gt.y;
        const int   ge0 = __float_as_int(gt.z);
        const int   ge1 = __float_as_int(gt.w);
        const int   q0  = ge0 >> 2, c0 = ge0 & 3;
        const int   q1  = ge1 >> 2, c1 = ge1 & 3;

        const float4* fr4 = f4 + (size_t)(n0 + tk) * (DDIM * NEXP / 4);
        float*        yr  = y + (size_t)(n0 + tk) * DDIM;

        if (q0 == q1) {                  // both experts in one float4 quarter
            float4 a[3];
            #pragma unroll
            for (int j = 0; j < 3; j++)
                a[j] = __ldcs(&fr4[(tid + j * 256) * 4 + q0]);
            #pragma unroll
            for (int j = 0; j < 3; j++)
                yr[tid + j * 256] = gw0 * quad_get(a[j], c0)
                                  + gw1 * quad_get(a[j], c1);
        } else {
            float4 a[3], bb[3];
            #pragma unroll
            for (int j = 0; j < 3; j++) {
                const int d = tid + j * 256;
                a[j]  = __ldcs(&fr4[d * 4 + q0]);
                bb[j] = __ldcs(&fr4[d * 4 + q1]);
            }
            #pragma unroll
            for (int j = 0; j < 3; j++)
                yr[tid + j * 256] = gw0 * quad_get(a[j],  c0)
                                  + gw1 * quad_get(bb[j], c1);
        }
    }
}

// ---------------- finalize: averages + trailing scalar ----------------
__global__ void finalize_kernel(float* __restrict__ soft_out,
                                float* __restrict__ hard_out,
                                float* __restrict__ zero_out)
{
    const int tid = threadIdx.x;         // 32 threads
    float sum = 0.f;
    #pragma unroll 8
    for (int bb = 0; bb < NBLK; bb++)
        sum += g_partials[bb * 32 + tid];
    sum *= (1.f / (float)NTOK);
    if (tid < 16) soft_out[tid] = sum;
    else          hard_out[tid - 16] = sum;
    if (tid == 0) *zero_out = 0.f;
}

// ---------------- launcher ----------------
extern "C" void kernel_launch(void* const* d_in, const int* in_sizes, int n_in,
                              void* d_out, int out_size)
{
    const float* f = (const float*)d_in[0];
    const float* x = (const float*)d_in[1];
    const float* W = (const float*)d_in[2];
    const float* b = (const float*)d_in[3];
    float* out = (float*)d_out;

    float* scratch = nullptr;
    cudaGetSymbolAddress((void**)&scratch, g_scratch);

    // flattened tuple layout: y | soft | hard | s_concat | 0
    const int FULL = NTOK * DDIM + 16 + 16 + NTOK * NEXP + 1;   // 6422561
    float *y, *soft, *hard, *sc, *zero;
    if (out_size == FULL) {
        y    = out;
        soft = out + NTOK * DDIM;
        hard = soft + 16;
        sc   = hard + 16;
        zero = sc + NTOK * NEXP;
    } else {
        y    = out;
        sc   = scratch;
        soft = scratch + NTOK * NEXP;
        hard = soft + 16;
        zero = hard + 16;
    }

    moe_fused_kernel<<<NBLK, 256>>>(f, x, W, b, y, sc);
    finalize_kernel<<<1, 32>>>(soft, hard, zero);
}

// round 7
// speedup vs baseline: 1.6897x; 1.6897x over previous
#include <cuda_runtime.h>
#include <math.h>

#define NTOK 8192
#define DDIM 768
#define NEXP 16
#define D4   192              // DDIM/4
#define GATE_BLOCKS 256       // 32 tokens per block
#define EPS  1e-5f

// ---------------- device scratch (no allocations allowed) ----------------
__device__ float4 g_gate[NTOK];                    // (w0, w1, e0 bits, e1 bits)
__device__ float  g_partials[GATE_BLOCKS * 32];    // per-block soft[16] + hard[16]

// ---------------- kernel 1: gate logits + top-2 softmax ----------------
// 256 blocks x 256 threads, 32 tokens/block, 4 tokens/warp.
// W staged to smem ONCE per block (48KB static, the limit; the soft/hard
// accumulator aliases it after the last read). Inner loop does 4 FFMA4 per
// conflict-free LDS.128 (consecutive lanes -> consecutive float4).
__global__ __launch_bounds__(256) void gate_kernel(
    const float* __restrict__ x,
    const float* __restrict__ W,
    const float* __restrict__ b,
    float* __restrict__ s_out)
{
    __shared__ float4 sW[3072];          // 48KB: W as float4 [e*192 + i]
    float* sAcc = (float*)sW;            // aliased AFTER all sW reads retire

    const int tid  = threadIdx.x;
    const int lane = tid & 31;
    const int wrp  = tid >> 5;           // 0..7
    const int n0   = blockIdx.x * 32 + wrp * 4;   // 4 tokens per warp

    // ---- stage W: 3072 float4, 12 per thread, coalesced ----
    const float4* W4 = (const float4*)W;
    for (int i = tid; i < 3072; i += 256) sW[i] = W4[i];
    __syncthreads();

    float acc[4][NEXP];
    #pragma unroll
    for (int j = 0; j < 4; j++)
        #pragma unroll
        for (int e = 0; e < NEXP; e++) acc[j][e] = 0.f;

    const float4* x4 = (const float4*)x;

    #pragma unroll
    for (int i = 0; i < 6; i++) {
        const int idx = i * 32 + lane;
        float4 xv[4];
        #pragma unroll
        for (int j = 0; j < 4; j++)
            xv[j] = x4[(size_t)(n0 + j) * D4 + idx];
        #pragma unroll
        for (int e = 0; e < NEXP; e++) {
            const float4 wv = sW[e * D4 + idx];   // conflict-free LDS.128
            #pragma unroll
            for (int j = 0; j < 4; j++) {
                acc[j][e] += xv[j].x * wv.x + xv[j].y * wv.y
                           + xv[j].z * wv.z + xv[j].w * wv.w;
            }
        }
    }

    // full-warp reduction for each (token, expert)
    #pragma unroll
    for (int j = 0; j < 4; j++)
        #pragma unroll
        for (int e = 0; e < NEXP; e++) {
            float s = acc[j][e];
            s += __shfl_xor_sync(0xffffffffu, s, 16);
            s += __shfl_xor_sync(0xffffffffu, s, 8);
            s += __shfl_xor_sync(0xffffffffu, s, 4);
            s += __shfl_xor_sync(0xffffffffu, s, 2);
            s += __shfl_xor_sync(0xffffffffu, s, 1);
            acc[j][e] = s;
        }

    // lane 0 finishes its 4 tokens; keep (w,e) pairs in regs across syncs
    float rw0[4], rw1[4];
    int   re0[4], re1[4];
    if (lane == 0) {
        #pragma unroll
        for (int j = 0; j < 4; j++) {
            const int n = n0 + j;
            float v[NEXP];
            #pragma unroll
            for (int e = 0; e < NEXP; e++) v[e] = acc[j][e] + b[e];

            // top-2 (ties -> lowest index first, matching lax.top_k)
            float b0 = v[0], b1 = -INFINITY;
            int   e0 = 0,    e1 = -1;
            #pragma unroll
            for (int e = 1; e < NEXP; e++) {
                if (v[e] > b0)      { b1 = b0; e1 = e0; b0 = v[e]; e0 = e; }
                else if (v[e] > b1) { b1 = v[e]; e1 = e; }
            }
            // stable softmax over the 2 selected logits (b1 <= b0)
            const float t   = expf(b1 - b0);
            const float inv = 1.f / (1.f + t);
            const float w0 = inv;
            const float w1 = t * inv;
            rw0[j] = w0; rw1[j] = w1; re0[j] = e0; re1[j] = e1;

            float4 gt;
            gt.x = w0; gt.y = w1;
            gt.z = __int_as_float(e0);
            gt.w = __int_as_float(e1);
            g_gate[n] = gt;

            // s_concat row: 1 where g < eps else 0 (g=0 for unselected)
            float4* srow = (float4*)(s_out + (size_t)n * NEXP);
            #pragma unroll
            for (int qq = 0; qq < 4; qq++) {
                float4 sv;
                #pragma unroll
                for (int c = 0; c < 4; c++) {
                    const int e = qq * 4 + c;
                    const float ge  = (e == e0) ? w0 : ((e == e1) ? w1 : 0.f);
                    const float val = (ge < EPS) ? 1.f : 0.f;
                    if      (c == 0) sv.x = val;
                    else if (c == 1) sv.y = val;
                    else if (c == 2) sv.z = val;
                    else             sv.w = val;
                }
                srow[qq] = sv;
            }
        }
    }

    // ---- soft/hard partials: sAcc aliases sW (all sW reads done) ----
    __syncthreads();
    if (tid < 32) sAcc[tid] = 0.f;
    __syncthreads();
    if (lane == 0) {
        #pragma unroll
        for (int j = 0; j < 4; j++) {
            atomicAdd(&sAcc[re0[j]], rw0[j]);
            atomicAdd(&sAcc[re1[j]], rw1[j]);
            atomicAdd(&sAcc[16 + re0[j]], (rw0[j] < EPS) ? 0.f : 1.f);
            atomicAdd(&sAcc[16 + re1[j]], (rw1[j] < EPS) ? 0.f : 1.f);
        }
    }
    __syncthreads();
    if (tid < 32) g_partials[blockIdx.x * 32 + tid] = sAcc[tid];
}

// ---------------- kernel 2: sparse combine (proven R1 version) ----------------
// One block per token; 384 threads x 2 elements. Only the 2 selected expert
// scalars per (n,d) are touched -> only the DRAM sectors containing them.
__global__ __launch_bounds__(384) void combine_kernel(
    const float* __restrict__ f,
    float* __restrict__ y)
{
    const int n = blockIdx.x;
    const float4 gt = g_gate[n];            // broadcast load
    const float w0 = gt.x, w1 = gt.y;
    const int   e0 = __float_as_int(gt.z);
    const int   e1 = __float_as_int(gt.w);

    const float* fr = f + (size_t)n * (DDIM * NEXP);
    float*       yr = y + (size_t)n * DDIM;

    const int d0 = threadIdx.x;
    const int d1 = threadIdx.x + 384;

    // batch all 4 loads before the stores for MLP
    const float a0 = __ldcs(fr + d0 * NEXP + e0);
    const float a1 = __ldcs(fr + d0 * NEXP + e1);
    const float c0 = __ldcs(fr + d1 * NEXP + e0);
    const float c1 = __ldcs(fr + d1 * NEXP + e1);

    yr[d0] = w0 * a0 + w1 * a1;
    yr[d1] = w0 * c0 + w1 * c1;
}

// ---------------- kernel 3: finalize (parallel, coalesced) ----------------
// 256 threads: thread tid sums g_partials[tid + k*256] (fully coalesced),
// then an 8-way smem fold per column.
__global__ void finalize_kernel(float* __restrict__ soft_out,
                                float* __restrict__ hard_out,
                                float* __restrict__ zero_out)
{
    __shared__ float sRed[256];
    const int tid = threadIdx.x;

    float sum = 0.f;
    #pragma unroll
    for (int k = 0; k < GATE_BLOCKS * 32 / 256; k++)   // 32 iterations
        sum += g_partials[tid + k * 256];
    sRed[tid] = sum;
    __syncthreads();

    if (tid < 32) {
        float s = 0.f;
        #pragma unroll
        for (int r = 0; r < 8; r++) s += sRed[r * 32 + tid];
        s *= (1.f / (float)NTOK);
        if (tid < 16) soft_out[tid] = s;
        else          hard_out[tid - 16] = s;
        if (tid == 0) *zero_out = 0.f;
    }
}

// ---------------- launcher ----------------
// Output layout proven in R1/R2/R4 (rel_err ~1e-7):
//   y [NTOK*DDIM] | soft [16] | hard [16] | s_concat [NTOK*NEXP] | 0 [1]
extern "C" void kernel_launch(void* const* d_in, const int* in_sizes, int n_in,
                              void* d_out, int out_size)
{
    const float* f = (const float*)d_in[0];
    const float* x = (const float*)d_in[1];
    const float* W = (const float*)d_in[2];
    const float* b = (const float*)d_in[3];
    float* out = (float*)d_out;

    float* y    = out;
    float* soft = out + NTOK * DDIM;
    float* hard = soft + 16;
    float* sc   = hard + 16;
    float* zero = sc + NTOK * NEXP;

    gate_kernel<<<GATE_BLOCKS, 256>>>(x, W, b, sc);
    combine_kernel<<<NTOK, 384>>>(f, y);
    finalize_kernel<<<1, 256>>>(soft, hard, zero);
}